// round 1
// baseline (speedup 1.0000x reference)
#include <cuda_runtime.h>
#include <math.h>

#define Bv 2
#define Tv 2048
#define Dv 2048
#define HKv 16
#define HVv 32
#define DKv 128
#define DVv 128
#define KEY_DIM 2048
#define VALUE_DIM 4096
#define CONV_DIM 8192
#define KCONV 4
#define EPSv 1e-6f
#define BT (Bv*Tv)

// ---------------- scratch (device globals; no allocation allowed) ----------
__device__ float g_mixed [BT*CONV_DIM];   // x @ w_qkv           (134 MB)
__device__ float g_mixedc[BT*CONV_DIM];   // conv+silu output    (134 MB)
__device__ float g_z     [BT*VALUE_DIM];  // x @ w_z             ( 67 MB)
__device__ float g_qn    [BT*KEY_DIM];    // l2norm'd q          ( 34 MB)
__device__ float g_kn    [BT*KEY_DIM];    // l2norm'd k          ( 34 MB)
__device__ float g_gg    [BT*HVv];        // decay log g
__device__ float g_beta  [BT*HVv];        // beta
__device__ float g_core  [BT*VALUE_DIM];  // scan output / gated ( 67 MB)

// ---------------- fp32 SGEMM: C[M,N] = A[M,K] @ B[K,N], row-major ----------
#define GBM 128
#define GBN 128
#define GBK 8
#define GTM 8
#define GTN 8

__global__ __launch_bounds__(256) void sgemm_kernel(
    const float* __restrict__ A, const float* __restrict__ B,
    float* __restrict__ C, int M, int N, int K)
{
    __shared__ float As[GBK][GBM];
    __shared__ float Bs[GBK][GBN];

    const int tid = threadIdx.x;
    const int bm = blockIdx.y * GBM;
    const int bn = blockIdx.x * GBN;

    const int arow = tid >> 1;            // 0..127
    const int acol = (tid & 1) * 4;       // 0 or 4
    const int brow = tid >> 5;            // 0..7
    const int bcol = (tid & 31) * 4;      // 0..124

    const int tx = (tid & 15) * GTN;      // 0..120
    const int ty = (tid >> 4) * GTM;      // 0..120

    float acc[GTM][GTN];
    #pragma unroll
    for (int i = 0; i < GTM; i++)
        #pragma unroll
        for (int j = 0; j < GTN; j++) acc[i][j] = 0.f;

    for (int k0 = 0; k0 < K; k0 += GBK) {
        float4 a4 = *(const float4*)(A + (size_t)(bm + arow) * K + k0 + acol);
        As[acol + 0][arow] = a4.x;
        As[acol + 1][arow] = a4.y;
        As[acol + 2][arow] = a4.z;
        As[acol + 3][arow] = a4.w;
        float4 b4 = *(const float4*)(B + (size_t)(k0 + brow) * N + bn + bcol);
        *(float4*)&Bs[brow][bcol] = b4;
        __syncthreads();

        #pragma unroll
        for (int kk = 0; kk < GBK; kk++) {
            float ra[GTM], rb[GTN];
            #pragma unroll
            for (int i = 0; i < GTM; i += 4)
                *(float4*)&ra[i] = *(const float4*)&As[kk][ty + i];
            #pragma unroll
            for (int j = 0; j < GTN; j += 4)
                *(float4*)&rb[j] = *(const float4*)&Bs[kk][tx + j];
            #pragma unroll
            for (int i = 0; i < GTM; i++)
                #pragma unroll
                for (int j = 0; j < GTN; j++)
                    acc[i][j] += ra[i] * rb[j];
        }
        __syncthreads();
    }

    #pragma unroll
    for (int i = 0; i < GTM; i++) {
        float* crow = C + (size_t)(bm + ty + i) * N + bn + tx;
        #pragma unroll
        for (int j = 0; j < GTN; j += 4) {
            float4 v = make_float4(acc[i][j], acc[i][j+1], acc[i][j+2], acc[i][j+3]);
            *(float4*)(crow + j) = v;
        }
    }
}

// ---------------- beta / g projections: x @ w_b, x @ w_a (+activations) ----
__global__ __launch_bounds__(256) void proj_ba_kernel(
    const float* __restrict__ x, const float* __restrict__ w_b,
    const float* __restrict__ w_a, const float* __restrict__ dt_bias,
    const float* __restrict__ A_log)
{
    __shared__ float partb[8][32];
    __shared__ float parta[8][32];
    const int row = blockIdx.x;                  // 0..BT-1
    const int warp = threadIdx.x >> 5;
    const int lane = threadIdx.x & 31;
    const float* xr = x + (size_t)row * Dv;

    float sb = 0.f, sa = 0.f;
    const int kbeg = warp * (Dv / 8);
    const int kend = kbeg + (Dv / 8);
    for (int kk = kbeg; kk < kend; kk++) {
        float xv = xr[kk];
        sb += xv * w_b[kk * HVv + lane];
        sa += xv * w_a[kk * HVv + lane];
    }
    partb[warp][lane] = sb;
    parta[warp][lane] = sa;
    __syncthreads();

    if (threadIdx.x < 32) {
        int col = threadIdx.x;
        float s = 0.f;
        #pragma unroll
        for (int w = 0; w < 8; w++) s += partb[w][col];
        g_beta[row * HVv + col] = 1.f / (1.f + expf(-s));
    } else if (threadIdx.x < 64) {
        int col = threadIdx.x - 32;
        float s = 0.f;
        #pragma unroll
        for (int w = 0; w < 8; w++) s += parta[w][col];
        float xsp = s + dt_bias[col];
        float sp = (xsp > 20.f) ? xsp : log1pf(expf(xsp));
        g_gg[row * HVv + col] = -expf(A_log[col]) * sp;
    }
}

// ---------------- causal depthwise conv (K=4) + SiLU ------------------------
__global__ void conv_silu_kernel(const float* __restrict__ conv_w)
{
    const int n4 = BT * CONV_DIM / 4;
    int idx = blockIdx.x * blockDim.x + threadIdx.x;
    if (idx >= n4) return;
    const int c4 = idx % (CONV_DIM / 4);
    const int bt = idx / (CONV_DIM / 4);
    const int t = bt % Tv;

    float4 acc = make_float4(0.f, 0.f, 0.f, 0.f);
    #pragma unroll
    for (int k = 0; k < KCONV; k++) {
        int tt = t + k - (KCONV - 1);
        if (tt >= 0) {
            float4 m = ((const float4*)g_mixed)[(size_t)(bt + k - (KCONV - 1)) * (CONV_DIM / 4) + c4];
            float4 w = ((const float4*)conv_w)[k * (CONV_DIM / 4) + c4];
            acc.x += m.x * w.x;
            acc.y += m.y * w.y;
            acc.z += m.z * w.z;
            acc.w += m.w * w.w;
        }
    }
    acc.x = acc.x / (1.f + expf(-acc.x));
    acc.y = acc.y / (1.f + expf(-acc.y));
    acc.z = acc.z / (1.f + expf(-acc.z));
    acc.w = acc.w / (1.f + expf(-acc.w));
    ((float4*)g_mixedc)[idx] = acc;
}

// ---------------- q/k l2-norm (one warp per head row) -----------------------
__global__ void qknorm_kernel()
{
    const int warp = (blockIdx.x * blockDim.x + threadIdx.x) >> 5;
    const int lane = threadIdx.x & 31;
    // warp indexes [0, BT*2*HK)
    const int bt = warp / (2 * HKv);
    const int r = warp % (2 * HKv);
    const int isk = r / HKv;
    const int h = r % HKv;

    const float* src = g_mixedc + (size_t)bt * CONV_DIM + isk * KEY_DIM + h * DKv;
    float* dst = (isk ? g_kn : g_qn) + ((size_t)bt * HKv + h) * DKv;

    float v[4];
    float ss = 0.f;
    #pragma unroll
    for (int i = 0; i < 4; i++) {
        v[i] = src[lane + 32 * i];
        ss += v[i] * v[i];
    }
    #pragma unroll
    for (int off = 16; off > 0; off >>= 1)
        ss += __shfl_xor_sync(0xFFFFFFFFu, ss, off);
    float sc = rsqrtf(ss + EPSv);
    if (!isk) sc *= 0.08838834764831845f;   // DK^-0.5, DK=128
    #pragma unroll
    for (int i = 0; i < 4; i++) dst[lane + 32 * i] = v[i] * sc;
}

// ---------------- sequential gated delta-rule scan --------------------------
// one CTA per (b, h): 128 threads; thread e owns state[:, e] in registers
__global__ __launch_bounds__(128, 1) void scan_kernel()
{
    const int b = blockIdx.x / HVv;
    const int h = blockIdx.x % HVv;
    const int kvh = h >> 1;                  // rep = HV/HK = 2
    const int e = threadIdx.x;

    float st[DKv];
    #pragma unroll
    for (int d = 0; d < DKv; d++) st[d] = 0.f;

    __shared__ float sq[2][DKv];
    __shared__ float sk[2][DKv];

    for (int t = 0; t < Tv; t++) {
        const int bt = b * Tv + t;
        const int buf = t & 1;
        sq[buf][e] = g_qn[((size_t)bt * HKv + kvh) * DKv + e];
        sk[buf][e] = g_kn[((size_t)bt * HKv + kvh) * DKv + e];
        const float vt = g_mixedc[(size_t)bt * CONV_DIM + 2 * KEY_DIM + h * DVv + e];
        const float gt = g_gg[bt * HVv + h];
        const float be = g_beta[bt * HVv + h];
        __syncthreads();

        const float dec = expf(gt);
        float kv = 0.f;
        #pragma unroll
        for (int d = 0; d < DKv; d++) {
            float s = st[d] * dec;
            st[d] = s;
            kv += sk[buf][d] * s;
        }
        const float delta = (vt - kv) * be;
        float out = 0.f;
        #pragma unroll
        for (int d = 0; d < DKv; d++) {
            float s = st[d] + sk[buf][d] * delta;
            st[d] = s;
            out += sq[buf][d] * s;
        }
        g_core[((size_t)bt * HVv + h) * DVv + e] = out;
    }
}

// ---------------- gated RMS norm epilogue (warp per (bt,h) row) --------------
__global__ void gate_kernel(const float* __restrict__ norm_w)
{
    const int row = (blockIdx.x * blockDim.x + threadIdx.x) >> 5;  // [0, BT*HV)
    const int lane = threadIdx.x & 31;
    const int bt = row / HVv;
    const int h = row % HVv;

    float* c = g_core + (size_t)row * DVv;
    const float* z = g_z + (size_t)bt * VALUE_DIM + h * DVv;

    float v[4];
    float ss = 0.f;
    #pragma unroll
    for (int i = 0; i < 4; i++) {
        v[i] = c[lane + 32 * i];
        ss += v[i] * v[i];
    }
    #pragma unroll
    for (int off = 16; off > 0; off >>= 1)
        ss += __shfl_xor_sync(0xFFFFFFFFu, ss, off);
    float rinv = rsqrtf(ss * (1.f / 128.f) + EPSv);
    #pragma unroll
    for (int i = 0; i < 4; i++) {
        int idx = lane + 32 * i;
        float zv = z[idx];
        float sig = 1.f / (1.f + expf(-zv));
        c[idx] = norm_w[idx] * v[i] * rinv * zv * sig;
    }
}

// ---------------- launch --------------------------------------------------
extern "C" void kernel_launch(void* const* d_in, const int* in_sizes, int n_in,
                              void* d_out, int out_size)
{
    const float* x       = (const float*)d_in[0];
    const float* w_qkv   = (const float*)d_in[1];
    const float* w_z     = (const float*)d_in[2];
    const float* w_b     = (const float*)d_in[3];
    const float* w_a     = (const float*)d_in[4];
    const float* conv_w  = (const float*)d_in[5];
    const float* dt_bias = (const float*)d_in[6];
    const float* A_log   = (const float*)d_in[7];
    const float* norm_w  = (const float*)d_in[8];
    const float* w_out   = (const float*)d_in[9];
    float* out = (float*)d_out;

    float *mixed, *z, *core;
    cudaGetSymbolAddress((void**)&mixed, g_mixed);
    cudaGetSymbolAddress((void**)&z,     g_z);
    cudaGetSymbolAddress((void**)&core,  g_core);

    // 1. big projections
    sgemm_kernel<<<dim3(CONV_DIM / GBN, BT / GBM), 256>>>(x, w_qkv, mixed, BT, CONV_DIM, Dv);
    sgemm_kernel<<<dim3(VALUE_DIM / GBN, BT / GBM), 256>>>(x, w_z, z, BT, VALUE_DIM, Dv);

    // 2. beta / g
    proj_ba_kernel<<<BT, 256>>>(x, w_b, w_a, dt_bias, A_log);

    // 3. conv + silu
    {
        int n4 = BT * CONV_DIM / 4;
        conv_silu_kernel<<<(n4 + 255) / 256, 256>>>(conv_w);
    }

    // 4. q/k l2norm
    qknorm_kernel<<<BT * 2 * HKv / 8, 256>>>();

    // 5. sequential scan
    scan_kernel<<<Bv * HVv, 128>>>();

    // 6. gated RMS norm
    gate_kernel<<<BT * HVv / 8, 256>>>(norm_w);

    // 7. output projection
    sgemm_kernel<<<dim3(Dv / GBN, BT / GBM), 256>>>(core, w_out, out, BT, Dv, VALUE_DIM);
}

// round 3
// speedup vs baseline: 1.9012x; 1.9012x over previous
#include <cuda_runtime.h>
#include <math.h>

#define Bv 2
#define Tv 2048
#define Dv 2048
#define HKv 16
#define HVv 32
#define DKv 128
#define DVv 128
#define KEY_DIM 2048
#define VALUE_DIM 4096
#define CONV_DIM 8192
#define KCONV 4
#define EPSv 1e-6f
#define BT (Bv*Tv)

// ---------------- scratch (device globals; no allocation allowed) ----------
__device__ float g_mixed [BT*CONV_DIM];     // x @ w_qkv
__device__ float g_mixedc[BT*CONV_DIM];     // conv+silu output
__device__ float g_z     [BT*VALUE_DIM];    // x @ w_z
__device__ float g_qn    [BT*KEY_DIM];      // l2norm'd q
__device__ float g_kn    [BT*KEY_DIM];      // l2norm'd k
__device__ float g_gg    [BT*HVv];          // decay log g
__device__ float g_beta  [BT*HVv];          // beta
__device__ float g_core  [BT*VALUE_DIM];    // scan output / gated

// ================= helpers =================================================
__device__ __forceinline__ unsigned smem_u32(const void* p) {
    unsigned a;
    asm("{ .reg .u64 t; cvta.to.shared.u64 t, %1; cvt.u32.u64 %0, t; }" : "=r"(a) : "l"(p));
    return a;
}
__device__ __forceinline__ unsigned cvt_tf32(float x) {
    unsigned u; asm("cvt.rna.tf32.f32 %0, %1;" : "=r"(u) : "f"(x));
    return u;
}
#define CP_ASYNC16(dst, src) asm volatile("cp.async.cg.shared.global [%0], [%1], 16;" :: "r"(dst), "l"(src))
#define CP_COMMIT()          asm volatile("cp.async.commit_group;")
#define CP_WAIT(n)           asm volatile("cp.async.wait_group %0;" :: "n"(n))

__device__ __forceinline__ void mma_tf32(float* c, const unsigned* a, const unsigned* b) {
    asm volatile(
        "mma.sync.aligned.m16n8k8.row.col.f32.tf32.tf32.f32 "
        "{%0,%1,%2,%3}, {%4,%5,%6,%7}, {%8,%9}, {%0,%1,%2,%3};"
        : "+f"(c[0]), "+f"(c[1]), "+f"(c[2]), "+f"(c[3])
        : "r"(a[0]), "r"(a[1]), "r"(a[2]), "r"(a[3]), "r"(b[0]), "r"(b[1]));
}

// ================= tf32 mma.sync GEMM: C[M,N] = A[M,K] @ B[K,N] ============
// CTA tile 128x128, BK=32, 3-stage cp.async pipeline, 8 warps of 64x32.
#define LDA 36
#define LDB 132
#define A_FLOATS (128*LDA)           // 4608
#define B_FLOATS (32*LDB)            // 4224
#define A_OFF(s) ((s)*A_FLOATS)
#define B_OFF(s) (3*A_FLOATS + (s)*B_FLOATS)
#define GEMM_SMEM ((3*A_FLOATS + 3*B_FLOATS)*4)

__global__ void __launch_bounds__(256, 2) mma_gemm_kernel(
    const float* __restrict__ A, const float* __restrict__ B,
    float* __restrict__ C, int M, int N, int K)
{
    extern __shared__ __align__(16) float dsm[];
    const unsigned sb = smem_u32(dsm);
    const int tid = threadIdx.x;
    const int wid = tid >> 5;
    const int lane = tid & 31;
    const int bm = blockIdx.y * 128;
    const int bn = blockIdx.x * 128;
    const int NT = K >> 5;

    const int warpM = (wid & 1) * 64;
    const int warpN = (wid >> 1) * 32;
    const int g = lane >> 2;        // group id 0..7
    const int tg = lane & 3;        // thread in group 0..3

    const float* gA = A + (size_t)bm * K;
    const float* gB = B + bn;

    // tile loader: A 128x32 (1024 16B chunks), B 32x128 (1024 chunks)
    auto load_tile = [&](int s, int t) {
        const int k0 = t << 5;
        #pragma unroll
        for (int i = 0; i < 4; i++) {
            int cid = tid + i * 256;
            {   // A
                int row = cid >> 3, c = cid & 7;
                CP_ASYNC16(sb + (A_OFF(s) + row * LDA + c * 4) * 4,
                           gA + (size_t)row * K + k0 + c * 4);
            }
            {   // B
                int row = cid >> 5, c = cid & 31;
                CP_ASYNC16(sb + (B_OFF(s) + row * LDB + c * 4) * 4,
                           gB + (size_t)(k0 + row) * N + c * 4);
            }
        }
        CP_COMMIT();
    };

    float acc[4][4][4];
    #pragma unroll
    for (int i = 0; i < 4; i++)
        #pragma unroll
        for (int j = 0; j < 4; j++)
            #pragma unroll
            for (int e = 0; e < 4; e++) acc[i][j][e] = 0.f;

    load_tile(0, 0);
    load_tile(1, 1);

    for (int t = 0; t < NT; t++) {
        if (t < NT - 2) { CP_WAIT(1); } else { CP_WAIT(0); }
        __syncthreads();
        if (t + 2 < NT) load_tile((t + 2) % 3, t + 2);

        const float* As = dsm + A_OFF(t % 3);
        const float* Bs = dsm + B_OFF(t % 3);

        #pragma unroll
        for (int kk = 0; kk < 4; kk++) {
            unsigned af[4][4], bf[4][2];
            #pragma unroll
            for (int mt = 0; mt < 4; mt++) {
                int r = warpM + mt * 16 + g;
                int c = kk * 8 + tg;
                af[mt][0] = cvt_tf32(As[r * LDA + c]);
                af[mt][1] = cvt_tf32(As[(r + 8) * LDA + c]);
                af[mt][2] = cvt_tf32(As[r * LDA + c + 4]);
                af[mt][3] = cvt_tf32(As[(r + 8) * LDA + c + 4]);
            }
            #pragma unroll
            for (int nt = 0; nt < 4; nt++) {
                int br = kk * 8 + tg;
                int bc = warpN + nt * 8 + g;
                bf[nt][0] = cvt_tf32(Bs[br * LDB + bc]);
                bf[nt][1] = cvt_tf32(Bs[(br + 4) * LDB + bc]);
            }
            #pragma unroll
            for (int mt = 0; mt < 4; mt++)
                #pragma unroll
                for (int nt = 0; nt < 4; nt++)
                    mma_tf32(acc[mt][nt], af[mt], bf[nt]);
        }
        __syncthreads();
    }

    // epilogue
    #pragma unroll
    for (int mt = 0; mt < 4; mt++) {
        #pragma unroll
        for (int nt = 0; nt < 4; nt++) {
            int r = bm + warpM + mt * 16 + g;
            int cN = bn + warpN + nt * 8 + tg * 2;
            *(float2*)(C + (size_t)r * N + cN) = make_float2(acc[mt][nt][0], acc[mt][nt][1]);
            *(float2*)(C + (size_t)(r + 8) * N + cN) = make_float2(acc[mt][nt][2], acc[mt][nt][3]);
        }
    }
}

// ================= beta / g projections (32 rows per block) ================
__global__ __launch_bounds__(256) void proj_ba_kernel(
    const float* __restrict__ x, const float* __restrict__ w_b,
    const float* __restrict__ w_a, const float* __restrict__ dt_bias,
    const float* __restrict__ A_log)
{
    __shared__ float sx[32][64];
    const int row0 = blockIdx.x * 32;
    const int tid = threadIdx.x;
    const int col = tid & 63;
    const int isa = (col >= 32);
    const int c32 = col & 31;
    const int rg = tid >> 6;
    const float* w = isa ? w_a : w_b;

    float acc[8];
    #pragma unroll
    for (int j = 0; j < 8; j++) acc[j] = 0.f;

    for (int k0 = 0; k0 < Dv; k0 += 64) {
        __syncthreads();
        #pragma unroll
        for (int i = 0; i < 2; i++) {
            int e = (tid + i * 256) * 4;
            int r = e >> 6, c = e & 63;
            *(float4*)&sx[r][c] = *(const float4*)(x + (size_t)(row0 + r) * Dv + k0 + c);
        }
        __syncthreads();
        for (int kk = 0; kk < 64; kk++) {
            float wv = w[(k0 + kk) * HVv + c32];
            #pragma unroll
            for (int j = 0; j < 8; j++)
                acc[j] += sx[rg * 8 + j][kk] * wv;
        }
    }
    #pragma unroll
    for (int j = 0; j < 8; j++) {
        int r = row0 + rg * 8 + j;
        if (!isa) {
            g_beta[r * HVv + c32] = 1.f / (1.f + expf(-acc[j]));
        } else {
            float xsp = acc[j] + dt_bias[c32];
            float sp = (xsp > 20.f) ? xsp : log1pf(expf(xsp));
            g_gg[r * HVv + c32] = -expf(A_log[c32]) * sp;
        }
    }
}

// ================= causal depthwise conv (K=4) + SiLU ======================
__global__ void conv_silu_kernel(const float* __restrict__ conv_w)
{
    const int n4 = BT * CONV_DIM / 4;
    int idx = blockIdx.x * blockDim.x + threadIdx.x;
    if (idx >= n4) return;
    const int c4 = idx % (CONV_DIM / 4);
    const int bt = idx / (CONV_DIM / 4);
    const int t = bt % Tv;

    float4 acc = make_float4(0.f, 0.f, 0.f, 0.f);
    #pragma unroll
    for (int k = 0; k < KCONV; k++) {
        int tt = t + k - (KCONV - 1);
        if (tt >= 0) {
            float4 m = ((const float4*)g_mixed)[(size_t)(bt + k - (KCONV - 1)) * (CONV_DIM / 4) + c4];
            float4 w = ((const float4*)conv_w)[k * (CONV_DIM / 4) + c4];
            acc.x += m.x * w.x;
            acc.y += m.y * w.y;
            acc.z += m.z * w.z;
            acc.w += m.w * w.w;
        }
    }
    acc.x = acc.x / (1.f + expf(-acc.x));
    acc.y = acc.y / (1.f + expf(-acc.y));
    acc.z = acc.z / (1.f + expf(-acc.z));
    acc.w = acc.w / (1.f + expf(-acc.w));
    ((float4*)g_mixedc)[idx] = acc;
}

// ================= q/k l2-norm =============================================
__global__ void qknorm_kernel()
{
    const int warp = (blockIdx.x * blockDim.x + threadIdx.x) >> 5;
    const int lane = threadIdx.x & 31;
    const int bt = warp / (2 * HKv);
    const int r = warp % (2 * HKv);
    const int isk = r / HKv;
    const int h = r % HKv;

    const float* src = g_mixedc + (size_t)bt * CONV_DIM + isk * KEY_DIM + h * DKv;
    float* dst = (isk ? g_kn : g_qn) + ((size_t)bt * HKv + h) * DKv;

    float v[4];
    float ss = 0.f;
    #pragma unroll
    for (int i = 0; i < 4; i++) {
        v[i] = src[lane + 32 * i];
        ss += v[i] * v[i];
    }
    #pragma unroll
    for (int off = 16; off > 0; off >>= 1)
        ss += __shfl_xor_sync(0xFFFFFFFFu, ss, off);
    float sc = rsqrtf(ss + EPSv);
    if (!isk) sc *= 0.08838834764831845f;
    #pragma unroll
    for (int i = 0; i < 4; i++) dst[lane + 32 * i] = v[i] * sc;
}

// ================= sequential gated delta-rule scan ========================
__global__ __launch_bounds__(128, 1) void scan_kernel()
{
    const int b = blockIdx.x / HVv;
    const int h = blockIdx.x % HVv;
    const int kvh = h >> 1;
    const int e = threadIdx.x;

    float st[DKv];
    #pragma unroll
    for (int d = 0; d < DKv; d++) st[d] = 0.f;

    __shared__ float sq[2][DKv];
    __shared__ float sk[2][DKv];

    for (int t = 0; t < Tv; t++) {
        const int bt = b * Tv + t;
        const int buf = t & 1;
        sq[buf][e] = g_qn[((size_t)bt * HKv + kvh) * DKv + e];
        sk[buf][e] = g_kn[((size_t)bt * HKv + kvh) * DKv + e];
        const float vt = g_mixedc[(size_t)bt * CONV_DIM + 2 * KEY_DIM + h * DVv + e];
        const float gt = g_gg[bt * HVv + h];
        const float be = g_beta[bt * HVv + h];
        __syncthreads();

        const float dec = expf(gt);
        float kv = 0.f;
        #pragma unroll
        for (int d = 0; d < DKv; d++) {
            float s = st[d] * dec;
            st[d] = s;
            kv += sk[buf][d] * s;
        }
        const float delta = (vt - kv) * be;
        float out = 0.f;
        #pragma unroll
        for (int d = 0; d < DKv; d++) {
            float s = st[d] + sk[buf][d] * delta;
            st[d] = s;
            out += sq[buf][d] * s;
        }
        g_core[((size_t)bt * HVv + h) * DVv + e] = out;
    }
}

// ================= gated RMS norm epilogue =================================
__global__ void gate_kernel(const float* __restrict__ norm_w)
{
    const int row = (blockIdx.x * blockDim.x + threadIdx.x) >> 5;
    const int lane = threadIdx.x & 31;
    const int bt = row / HVv;
    const int h = row % HVv;

    float* c = g_core + (size_t)row * DVv;
    const float* z = g_z + (size_t)bt * VALUE_DIM + h * DVv;

    float v[4];
    float ss = 0.f;
    #pragma unroll
    for (int i = 0; i < 4; i++) {
        v[i] = c[lane + 32 * i];
        ss += v[i] * v[i];
    }
    #pragma unroll
    for (int off = 16; off > 0; off >>= 1)
        ss += __shfl_xor_sync(0xFFFFFFFFu, ss, off);
    float rinv = rsqrtf(ss * (1.f / 128.f) + EPSv);
    #pragma unroll
    for (int i = 0; i < 4; i++) {
        int idx = lane + 32 * i;
        float zv = z[idx];
        float sig = 1.f / (1.f + expf(-zv));
        c[idx] = norm_w[idx] * v[i] * rinv * zv * sig;
    }
}

// ================= launch ==================================================
extern "C" void kernel_launch(void* const* d_in, const int* in_sizes, int n_in,
                              void* d_out, int out_size)
{
    const float* x       = (const float*)d_in[0];
    const float* w_qkv   = (const float*)d_in[1];
    const float* w_z     = (const float*)d_in[2];
    const float* w_b     = (const float*)d_in[3];
    const float* w_a     = (const float*)d_in[4];
    const float* conv_w  = (const float*)d_in[5];
    const float* dt_bias = (const float*)d_in[6];
    const float* A_log   = (const float*)d_in[7];
    const float* norm_w  = (const float*)d_in[8];
    const float* w_out   = (const float*)d_in[9];
    float* out = (float*)d_out;

    float *mixed, *z, *core;
    cudaGetSymbolAddress((void**)&mixed, g_mixed);
    cudaGetSymbolAddress((void**)&z,     g_z);
    cudaGetSymbolAddress((void**)&core,  g_core);

    cudaFuncSetAttribute(mma_gemm_kernel,
                         cudaFuncAttributeMaxDynamicSharedMemorySize, GEMM_SMEM);

    // 1. big projections (tensor core tf32 via mma.sync)
    mma_gemm_kernel<<<dim3(CONV_DIM / 128, BT / 128), 256, GEMM_SMEM>>>(x, w_qkv, mixed, BT, CONV_DIM, Dv);
    mma_gemm_kernel<<<dim3(VALUE_DIM / 128, BT / 128), 256, GEMM_SMEM>>>(x, w_z, z, BT, VALUE_DIM, Dv);

    // 2. beta / g
    proj_ba_kernel<<<BT / 32, 256>>>(x, w_b, w_a, dt_bias, A_log);

    // 3. conv + silu
    conv_silu_kernel<<<(BT * CONV_DIM / 4 + 255) / 256, 256>>>(conv_w);

    // 4. q/k l2norm
    qknorm_kernel<<<BT * 2 * HKv / 8, 256>>>();

    // 5. sequential scan
    scan_kernel<<<Bv * HVv, 128>>>();

    // 6. gated RMS norm
    gate_kernel<<<BT * HVv / 8, 256>>>(norm_w);

    // 7. output projection
    mma_gemm_kernel<<<dim3(Dv / 128, BT / 128), 256, GEMM_SMEM>>>(core, w_out, out, BT, Dv, VALUE_DIM);
}

// round 4
// speedup vs baseline: 2.6923x; 1.4161x over previous
#include <cuda_runtime.h>
#include <math.h>

#define Bv 2
#define Tv 2048
#define Dv 2048
#define HKv 16
#define HVv 32
#define DKv 128
#define DVv 128
#define KEY_DIM 2048
#define VALUE_DIM 4096
#define CONV_DIM 8192
#define KCONV 4
#define EPSv 1e-6f
#define BT (Bv*Tv)

// ---------------- scratch (device globals; no allocation allowed) ----------
__device__ float g_mixed [BT*CONV_DIM];     // x @ w_qkv
__device__ float g_mixedc[BT*CONV_DIM];     // conv+silu output
__device__ float g_z     [BT*VALUE_DIM];    // x @ w_z
__device__ float g_qn    [BT*KEY_DIM];      // l2norm'd q
__device__ float g_kn    [BT*KEY_DIM];      // l2norm'd k
__device__ float g_gg    [BT*HVv];          // decay log g
__device__ float g_beta  [BT*HVv];          // beta
__device__ float g_core  [BT*VALUE_DIM];    // scan output / gated (tf32-rounded)
__device__ float g_xr    [BT*Dv];           // tf32-rounded x
__device__ float g_wqkvr [Dv*CONV_DIM];     // tf32-rounded w_qkv
__device__ float g_wzr   [Dv*VALUE_DIM];    // tf32-rounded w_z
__device__ float g_woutr [VALUE_DIM*Dv];    // tf32-rounded w_out

// ================= helpers =================================================
__device__ __forceinline__ unsigned smem_u32(const void* p) {
    unsigned a;
    asm("{ .reg .u64 t; cvta.to.shared.u64 t, %1; cvt.u32.u64 %0, t; }" : "=r"(a) : "l"(p));
    return a;
}
__device__ __forceinline__ float rtf32(float x) {
    unsigned u; asm("cvt.rna.tf32.f32 %0, %1;" : "=r"(u) : "f"(x));
    return __uint_as_float(u);
}
#define CP_ASYNC16(dst, src) asm volatile("cp.async.cg.shared.global [%0], [%1], 16;" :: "r"(dst), "l"(src))
#define CP_COMMIT()          asm volatile("cp.async.commit_group;")
#define CP_WAIT(n)           asm volatile("cp.async.wait_group %0;" :: "n"(n))

__device__ __forceinline__ void mma_tf32(float* c, const unsigned* a, const unsigned* b) {
    asm volatile(
        "mma.sync.aligned.m16n8k8.row.col.f32.tf32.tf32.f32 "
        "{%0,%1,%2,%3}, {%4,%5,%6,%7}, {%8,%9}, {%0,%1,%2,%3};"
        : "+f"(c[0]), "+f"(c[1]), "+f"(c[2]), "+f"(c[3])
        : "r"(a[0]), "r"(a[1]), "r"(a[2]), "r"(a[3]), "r"(b[0]), "r"(b[1]));
}

// ================= tf32 round (elementwise, float4, grid-stride) ==========
__global__ void round_copy_kernel(const float* __restrict__ src,
                                  float* __restrict__ dst, int n4)
{
    int i = blockIdx.x * blockDim.x + threadIdx.x;
    if (i >= n4) return;
    float4 v = ((const float4*)src)[i];
    v.x = rtf32(v.x); v.y = rtf32(v.y); v.z = rtf32(v.z); v.w = rtf32(v.w);
    ((float4*)dst)[i] = v;
}

// ================= tf32 mma.sync GEMM: C[M,N] = A[M,K] @ B[K,N] ============
// Inputs MUST be pre-rounded to tf32. CTA 128x128, BK=32, 3-stage cp.async.
#define LDA 36
#define LDB 132
#define A_FLOATS (128*LDA)
#define B_FLOATS (32*LDB)
#define A_OFF(s) ((s)*A_FLOATS)
#define B_OFF(s) (3*A_FLOATS + (s)*B_FLOATS)
#define GEMM_SMEM ((3*A_FLOATS + 3*B_FLOATS)*4)

__global__ void __launch_bounds__(256, 2) mma_gemm_kernel(
    const float* __restrict__ A, const float* __restrict__ B,
    float* __restrict__ C, int M, int N, int K)
{
    extern __shared__ __align__(16) float dsm[];
    const unsigned sb = smem_u32(dsm);
    const int tid = threadIdx.x;
    const int wid = tid >> 5;
    const int lane = tid & 31;
    const int bm = blockIdx.y * 128;
    const int bn = blockIdx.x * 128;
    const int NT = K >> 5;

    const int warpM = (wid & 1) * 64;
    const int warpN = (wid >> 1) * 32;
    const int g = lane >> 2;
    const int tg = lane & 3;

    const float* gA = A + (size_t)bm * K;
    const float* gB = B + bn;

    auto load_tile = [&](int s, int t) {
        const int k0 = t << 5;
        #pragma unroll
        for (int i = 0; i < 4; i++) {
            int cid = tid + i * 256;
            {   // A: 128 rows x 32 cols
                int row = cid >> 3, c = cid & 7;
                CP_ASYNC16(sb + (A_OFF(s) + row * LDA + c * 4) * 4,
                           gA + (size_t)row * K + k0 + c * 4);
            }
            {   // B: 32 rows x 128 cols
                int row = cid >> 5, c = cid & 31;
                CP_ASYNC16(sb + (B_OFF(s) + row * LDB + c * 4) * 4,
                           gB + (size_t)(k0 + row) * N + c * 4);
            }
        }
        CP_COMMIT();
    };

    float acc[4][4][4];
    #pragma unroll
    for (int i = 0; i < 4; i++)
        #pragma unroll
        for (int j = 0; j < 4; j++)
            #pragma unroll
            for (int e = 0; e < 4; e++) acc[i][j][e] = 0.f;

    load_tile(0, 0);
    load_tile(1, 1);

    for (int t = 0; t < NT; t++) {
        if (t < NT - 2) { CP_WAIT(1); } else { CP_WAIT(0); }
        __syncthreads();
        if (t + 2 < NT) load_tile((t + 2) % 3, t + 2);

        const float* As = dsm + A_OFF(t % 3);
        const float* Bs = dsm + B_OFF(t % 3);

        #pragma unroll
        for (int kk = 0; kk < 4; kk++) {
            unsigned af[4][4], bf[4][2];
            #pragma unroll
            for (int mt = 0; mt < 4; mt++) {
                int r = warpM + mt * 16 + g;
                int c = kk * 8 + tg;
                af[mt][0] = __float_as_uint(As[r * LDA + c]);
                af[mt][1] = __float_as_uint(As[(r + 8) * LDA + c]);
                af[mt][2] = __float_as_uint(As[r * LDA + c + 4]);
                af[mt][3] = __float_as_uint(As[(r + 8) * LDA + c + 4]);
            }
            #pragma unroll
            for (int nt = 0; nt < 4; nt++) {
                int br = kk * 8 + tg;
                int bc = warpN + nt * 8 + g;
                bf[nt][0] = __float_as_uint(Bs[br * LDB + bc]);
                bf[nt][1] = __float_as_uint(Bs[(br + 4) * LDB + bc]);
            }
            #pragma unroll
            for (int mt = 0; mt < 4; mt++)
                #pragma unroll
                for (int nt = 0; nt < 4; nt++)
                    mma_tf32(acc[mt][nt], af[mt], bf[nt]);
        }
        __syncthreads();
    }

    #pragma unroll
    for (int mt = 0; mt < 4; mt++) {
        #pragma unroll
        for (int nt = 0; nt < 4; nt++) {
            int r = bm + warpM + mt * 16 + g;
            int cN = bn + warpN + nt * 8 + tg * 2;
            *(float2*)(C + (size_t)r * N + cN) = make_float2(acc[mt][nt][0], acc[mt][nt][1]);
            *(float2*)(C + (size_t)(r + 8) * N + cN) = make_float2(acc[mt][nt][2], acc[mt][nt][3]);
        }
    }
}

// ================= beta / g projections (32 rows per block) ================
__global__ __launch_bounds__(256) void proj_ba_kernel(
    const float* __restrict__ x, const float* __restrict__ w_b,
    const float* __restrict__ w_a, const float* __restrict__ dt_bias,
    const float* __restrict__ A_log)
{
    __shared__ float sx[32][64];
    const int row0 = blockIdx.x * 32;
    const int tid = threadIdx.x;
    const int col = tid & 63;
    const int isa = (col >= 32);
    const int c32 = col & 31;
    const int rg = tid >> 6;
    const float* w = isa ? w_a : w_b;

    float acc[8];
    #pragma unroll
    for (int j = 0; j < 8; j++) acc[j] = 0.f;

    for (int k0 = 0; k0 < Dv; k0 += 64) {
        __syncthreads();
        #pragma unroll
        for (int i = 0; i < 2; i++) {
            int e = (tid + i * 256) * 4;
            int r = e >> 6, c = e & 63;
            *(float4*)&sx[r][c] = *(const float4*)(x + (size_t)(row0 + r) * Dv + k0 + c);
        }
        __syncthreads();
        for (int kk = 0; kk < 64; kk++) {
            float wv = w[(k0 + kk) * HVv + c32];
            #pragma unroll
            for (int j = 0; j < 8; j++)
                acc[j] += sx[rg * 8 + j][kk] * wv;
        }
    }
    #pragma unroll
    for (int j = 0; j < 8; j++) {
        int r = row0 + rg * 8 + j;
        if (!isa) {
            g_beta[r * HVv + c32] = 1.f / (1.f + expf(-acc[j]));
        } else {
            float xsp = acc[j] + dt_bias[c32];
            float sp = (xsp > 20.f) ? xsp : log1pf(expf(xsp));
            g_gg[r * HVv + c32] = -expf(A_log[c32]) * sp;
        }
    }
}

// ================= causal depthwise conv (K=4) + SiLU ======================
__global__ void conv_silu_kernel(const float* __restrict__ conv_w)
{
    const int n4 = BT * CONV_DIM / 4;
    int idx = blockIdx.x * blockDim.x + threadIdx.x;
    if (idx >= n4) return;
    const int c4 = idx % (CONV_DIM / 4);
    const int bt = idx / (CONV_DIM / 4);
    const int t = bt % Tv;

    float4 acc = make_float4(0.f, 0.f, 0.f, 0.f);
    #pragma unroll
    for (int k = 0; k < KCONV; k++) {
        int tt = t + k - (KCONV - 1);
        if (tt >= 0) {
            float4 m = ((const float4*)g_mixed)[(size_t)(bt + k - (KCONV - 1)) * (CONV_DIM / 4) + c4];
            float4 w = ((const float4*)conv_w)[k * (CONV_DIM / 4) + c4];
            acc.x += m.x * w.x;
            acc.y += m.y * w.y;
            acc.z += m.z * w.z;
            acc.w += m.w * w.w;
        }
    }
    acc.x = acc.x / (1.f + expf(-acc.x));
    acc.y = acc.y / (1.f + expf(-acc.y));
    acc.z = acc.z / (1.f + expf(-acc.z));
    acc.w = acc.w / (1.f + expf(-acc.w));
    ((float4*)g_mixedc)[idx] = acc;
}

// ================= q/k l2-norm =============================================
__global__ void qknorm_kernel()
{
    const int warp = (blockIdx.x * blockDim.x + threadIdx.x) >> 5;
    const int lane = threadIdx.x & 31;
    const int bt = warp / (2 * HKv);
    const int r = warp % (2 * HKv);
    const int isk = r / HKv;
    const int h = r % HKv;

    const float* src = g_mixedc + (size_t)bt * CONV_DIM + isk * KEY_DIM + h * DKv;
    float* dst = (isk ? g_kn : g_qn) + ((size_t)bt * HKv + h) * DKv;

    float v[4];
    float ss = 0.f;
    #pragma unroll
    for (int i = 0; i < 4; i++) {
        v[i] = src[lane + 32 * i];
        ss += v[i] * v[i];
    }
    #pragma unroll
    for (int off = 16; off > 0; off >>= 1)
        ss += __shfl_xor_sync(0xFFFFFFFFu, ss, off);
    float sc = rsqrtf(ss + EPSv);
    if (!isk) sc *= 0.08838834764831845f;
    #pragma unroll
    for (int i = 0; i < 4; i++) dst[lane + 32 * i] = v[i] * sc;
}

// ================= sequential gated delta-rule scan ========================
// 128 CTAs: one per (b, h, column-half). 128 threads: (col, d-half).
// Lane pairs (xor 1) split the d-dimension; kv/out combined via shfl.
__global__ __launch_bounds__(128, 1) void scan_kernel()
{
    const int unit = blockIdx.x >> 1;        // (b,h)
    const int chalf = blockIdx.x & 1;        // column half
    const int b = unit / HVv;
    const int h = unit % HVv;
    const int kvh = h >> 1;

    const int tid = threadIdx.x;
    const int colL = tid >> 1;               // 0..63 local column
    const int dhalf = tid & 1;               // d-half
    const int gcol = chalf * 64 + colL;      // global column in DV
    const int dbase = dhalf * 64;

    float st[64];
    #pragma unroll
    for (int i = 0; i < 64; i++) st[i] = 0.f;

    __shared__ float sq[2][DKv];
    __shared__ float sk[2][DKv];
    __shared__ float sv[2][64];

    const size_t qkbase0 = ((size_t)(b * Tv) * HKv + kvh) * DKv;
    const size_t vbase0 = (size_t)(b * Tv) * CONV_DIM + 2 * KEY_DIM + h * DVv;

    // prefetch t = 0
    float rq = g_qn[qkbase0 + tid];
    float rk = g_kn[qkbase0 + tid];
    float rv = (tid < 64) ? g_mixedc[vbase0 + chalf * 64 + tid] : 0.f;
    float rg = g_gg[(b * Tv) * HVv + h];
    float rb = g_beta[(b * Tv) * HVv + h];

    for (int t = 0; t < Tv; t++) {
        const int buf = t & 1;
        sq[buf][tid] = rq;
        sk[buf][tid] = rk;
        if (tid < 64) sv[buf][tid] = rv;
        const float gt = rg, be = rb;
        __syncthreads();

        // prefetch t+1 (clamped address; values unused on last iter)
        const int tn = (t + 1 < Tv) ? (t + 1) : t;
        const size_t qkb = qkbase0 + (size_t)tn * (HKv * DKv);
        rq = g_qn[qkb + tid];
        rk = g_kn[qkb + tid];
        if (tid < 64) rv = g_mixedc[vbase0 + (size_t)tn * CONV_DIM + chalf * 64 + tid];
        rg = g_gg[(b * Tv + tn) * HVv + h];
        rb = g_beta[(b * Tv + tn) * HVv + h];

        const float dec = expf(gt);
        // pass 1: decay + kv partial over this d-half
        float kv0 = 0.f, kv1 = 0.f, kv2 = 0.f, kv3 = 0.f;
        #pragma unroll
        for (int i = 0; i < 64; i += 4) {
            float4 k4 = *(const float4*)&sk[buf][dbase + i];
            float s0 = st[i]     * dec;
            float s1 = st[i + 1] * dec;
            float s2 = st[i + 2] * dec;
            float s3 = st[i + 3] * dec;
            st[i] = s0; st[i + 1] = s1; st[i + 2] = s2; st[i + 3] = s3;
            kv0 += k4.x * s0; kv1 += k4.y * s1; kv2 += k4.z * s2; kv3 += k4.w * s3;
        }
        float kv = (kv0 + kv1) + (kv2 + kv3);
        kv += __shfl_xor_sync(0xFFFFFFFFu, kv, 1);

        const float vt = sv[buf][colL];
        const float delta = (vt - kv) * be;

        // pass 2: rank-1 update + out partial
        float o0 = 0.f, o1 = 0.f, o2 = 0.f, o3 = 0.f;
        #pragma unroll
        for (int i = 0; i < 64; i += 4) {
            float4 k4 = *(const float4*)&sk[buf][dbase + i];
            float4 q4 = *(const float4*)&sq[buf][dbase + i];
            float s0 = st[i]     + k4.x * delta;
            float s1 = st[i + 1] + k4.y * delta;
            float s2 = st[i + 2] + k4.z * delta;
            float s3 = st[i + 3] + k4.w * delta;
            st[i] = s0; st[i + 1] = s1; st[i + 2] = s2; st[i + 3] = s3;
            o0 += q4.x * s0; o1 += q4.y * s1; o2 += q4.z * s2; o3 += q4.w * s3;
        }
        float out = (o0 + o1) + (o2 + o3);
        out += __shfl_xor_sync(0xFFFFFFFFu, out, 1);
        if (dhalf == 0)
            g_core[(((size_t)(b * Tv + t)) * HVv + h) * DVv + gcol] = out;
    }
}

// ================= gated RMS norm epilogue (writes tf32-rounded) ============
__global__ void gate_kernel(const float* __restrict__ norm_w)
{
    const int row = (blockIdx.x * blockDim.x + threadIdx.x) >> 5;
    const int lane = threadIdx.x & 31;
    const int bt = row / HVv;
    const int h = row % HVv;

    float* c = g_core + (size_t)row * DVv;
    const float* z = g_z + (size_t)bt * VALUE_DIM + h * DVv;

    float v[4];
    float ss = 0.f;
    #pragma unroll
    for (int i = 0; i < 4; i++) {
        v[i] = c[lane + 32 * i];
        ss += v[i] * v[i];
    }
    #pragma unroll
    for (int off = 16; off > 0; off >>= 1)
        ss += __shfl_xor_sync(0xFFFFFFFFu, ss, off);
    float rinv = rsqrtf(ss * (1.f / 128.f) + EPSv);
    #pragma unroll
    for (int i = 0; i < 4; i++) {
        int idx = lane + 32 * i;
        float zv = z[idx];
        float sig = 1.f / (1.f + expf(-zv));
        c[idx] = rtf32(norm_w[idx] * v[i] * rinv * zv * sig);
    }
}

// ================= launch ==================================================
extern "C" void kernel_launch(void* const* d_in, const int* in_sizes, int n_in,
                              void* d_out, int out_size)
{
    const float* x       = (const float*)d_in[0];
    const float* w_qkv   = (const float*)d_in[1];
    const float* w_z     = (const float*)d_in[2];
    const float* w_b     = (const float*)d_in[3];
    const float* w_a     = (const float*)d_in[4];
    const float* conv_w  = (const float*)d_in[5];
    const float* dt_bias = (const float*)d_in[6];
    const float* A_log   = (const float*)d_in[7];
    const float* norm_w  = (const float*)d_in[8];
    const float* w_out   = (const float*)d_in[9];
    float* out = (float*)d_out;

    float *mixed, *z, *core, *xr, *wqkvr, *wzr, *woutr;
    cudaGetSymbolAddress((void**)&mixed, g_mixed);
    cudaGetSymbolAddress((void**)&z,     g_z);
    cudaGetSymbolAddress((void**)&core,  g_core);
    cudaGetSymbolAddress((void**)&xr,    g_xr);
    cudaGetSymbolAddress((void**)&wqkvr, g_wqkvr);
    cudaGetSymbolAddress((void**)&wzr,   g_wzr);
    cudaGetSymbolAddress((void**)&woutr, g_woutr);

    cudaFuncSetAttribute(mma_gemm_kernel,
                         cudaFuncAttributeMaxDynamicSharedMemorySize, GEMM_SMEM);

    // 0. RNE tf32 pre-rounding of GEMM operands
    round_copy_kernel<<<(BT * Dv / 4 + 255) / 256, 256>>>(x, xr, BT * Dv / 4);
    round_copy_kernel<<<(Dv * CONV_DIM / 4 + 255) / 256, 256>>>(w_qkv, wqkvr, Dv * CONV_DIM / 4);
    round_copy_kernel<<<(Dv * VALUE_DIM / 4 + 255) / 256, 256>>>(w_z, wzr, Dv * VALUE_DIM / 4);
    round_copy_kernel<<<(VALUE_DIM * Dv / 4 + 255) / 256, 256>>>(w_out, woutr, VALUE_DIM * Dv / 4);

    // 1. big projections (tensor core tf32 via mma.sync)
    mma_gemm_kernel<<<dim3(CONV_DIM / 128, BT / 128), 256, GEMM_SMEM>>>(xr, wqkvr, mixed, BT, CONV_DIM, Dv);
    mma_gemm_kernel<<<dim3(VALUE_DIM / 128, BT / 128), 256, GEMM_SMEM>>>(xr, wzr, z, BT, VALUE_DIM, Dv);

    // 2. beta / g
    proj_ba_kernel<<<BT / 32, 256>>>(x, w_b, w_a, dt_bias, A_log);

    // 3. conv + silu
    conv_silu_kernel<<<(BT * CONV_DIM / 4 + 255) / 256, 256>>>(conv_w);

    // 4. q/k l2norm
    qknorm_kernel<<<BT * 2 * HKv / 8, 256>>>();

    // 5. sequential scan (128 CTAs, d-split lane pairs)
    scan_kernel<<<Bv * HVv * 2, 128>>>();

    // 6. gated RMS norm (+ tf32 round for final GEMM)
    gate_kernel<<<BT * HVv / 8, 256>>>(norm_w);

    // 7. output projection
    mma_gemm_kernel<<<dim3(Dv / 128, BT / 128), 256, GEMM_SMEM>>>(core, woutr, out, BT, Dv, VALUE_DIM);
}